// round 8
// baseline (speedup 1.0000x reference)
#include <cuda_runtime.h>
#include <cuda_bf16.h>
#include <cstdint>

// out[t, :] = W[x[t], :] + b    t in [0, 8192), D = 2048
//
// Model update: kernel is LSU-ISSUE bound, not DRAM/latency bound.
// STG.128 costs ~12 LSU cycles/warp-instr (B300 measured) -> ~28K LSU
// cycles/SM total for LDG+STG path = ~16us, matching the observed plateau.
// Fix: stores leave via smem + cp.async.bulk (TMA engine) instead of STG.
// Per-warp LSU cost drops 32 -> ~16 cycles; store issue is ~free (1 thread),
// and each row goes out as one contiguous 8KB burst (better DRAM write
// efficiency than scattered 128B sectors).

#define D_MODEL 2048
#define D4      (D_MODEL / 4)      // 512 float4 per row
#define ROW_BYTES (D_MODEL * 4)    // 8192 B
#define TOKENS  8192
#define NTHR    256

__device__ __forceinline__ uint32_t smem_u32(const void* p) {
    uint32_t a;
    asm("{ .reg .u64 t; cvta.to.shared.u64 t, %1; cvt.u32.u64 %0, t; }"
        : "=r"(a) : "l"(p));
    return a;
}

__global__ __launch_bounds__(NTHR, 8)
void embed_gather_bulkst(const int* __restrict__ x,
                         const float4* __restrict__ W4,
                         const float4* __restrict__ b4,
                         float4* __restrict__ out4) {
    __shared__ alignas(128) float4 buf[D4];   // 8 KB staging for one row

    const int t = blockIdx.x;
    const long long row = (long long)x[t];
    const float4* __restrict__ src = W4 + row * D4;

    const int c0 = threadIdx.x;
    const int c1 = threadIdx.x + NTHR;

    // independent, front-batched
    float4 v0 = src[c0];
    float4 v1 = src[c1];
    float4 bb0 = b4[c0];
    float4 bb1 = b4[c1];

    v0.x += bb0.x; v0.y += bb0.y; v0.z += bb0.z; v0.w += bb0.w;
    v1.x += bb1.x; v1.y += bb1.y; v1.z += bb1.z; v1.w += bb1.w;

    buf[c0] = v0;                              // STS.128 (cheap on LSU)
    buf[c1] = v1;

    // order generic smem writes before the async-proxy bulk read
    asm volatile("fence.proxy.async.shared::cta;" ::: "memory");
    __syncthreads();

    if (threadIdx.x == 0) {
        float4* dst = out4 + (long long)t * D4;
        asm volatile(
            "cp.async.bulk.global.shared::cta.bulk_group [%0], [%1], %2;"
            :: "l"(dst), "r"(smem_u32(buf)), "r"((uint32_t)ROW_BYTES)
            : "memory");
        asm volatile("cp.async.bulk.commit_group;" ::: "memory");
        // smem must stay live until the bulk engine has read it
        asm volatile("cp.async.bulk.wait_group 0;" ::: "memory");
    }
}

extern "C" void kernel_launch(void* const* d_in, const int* in_sizes, int n_in,
                              void* d_out, int out_size) {
    const int*    x = (const int*)d_in[0];        // [4, 2048] int32
    const float4* W = (const float4*)d_in[1];     // [50257, 2048] f32
    const float4* b = (const float4*)d_in[2];     // [2048] f32
    float4* out = (float4*)d_out;                 // [4, 2048, 2048] f32

    embed_gather_bulkst<<<TOKENS, NTHR>>>(x, W, b, out);
}

// round 9
// speedup vs baseline: 1.6857x; 1.6857x over previous
#include <cuda_runtime.h>
#include <cuda_bf16.h>

// out[t, :] = W[x[t], :] + b    t in [0, 8192), D = 2048
//
// Model: all prior variants plateau at ~19-20us with DRAM ~48% and nothing
// saturated. Cause: load duty cycle. Each short-lived CTA serializes
// idx-load -> W-loads -> add/store/exit, so loads are in flight only ~half
// of warp residency; Little's law caps BW at ~half the roof. Fix: persistent
// CTAs with a software pipeline — next token's W loads issue while the
// current token is consumed; indices prefetched two iterations ahead so the
// idx->row dependency is fully hidden. Stores stay evict-first (.cs).

#define D_MODEL 2048
#define D4      (D_MODEL / 4)   // 512 float4 per row
#define TOKENS  8192
#define GRID    1184            // 8 CTAs/SM * 148 SMs
#define NTHR    256

__global__ __launch_bounds__(NTHR, 8)
void embed_gather_pipe(const int* __restrict__ x,
                       const float4* __restrict__ W4,
                       const float4* __restrict__ b4,
                       float4* __restrict__ out4) {
    const int c0 = threadIdx.x;
    const int c1 = threadIdx.x + NTHR;

    const float4 bb0 = b4[c0];
    const float4 bb1 = b4[c1];

    int t = blockIdx.x;                      // GRID < TOKENS, always valid
    int t1 = t + GRID;

    // prologue: current row loads + next index
    long long r_cur = (long long)__ldg(x + t);
    long long r_nxt = (t1 < TOKENS) ? (long long)__ldg(x + t1) : 0;

    float4 a0 = W4[r_cur * D4 + c0];
    float4 a1 = W4[r_cur * D4 + c1];

    for (;;) {
        const bool have_next = (t1 < TOKENS);

        // prefetch index two ahead (hides idx->row dependency)
        const int t2 = t1 + GRID;
        const long long r_nxt2 = (t2 < TOKENS) ? (long long)__ldg(x + t2) : 0;

        // issue next row's loads BEFORE consuming current (independent of stores)
        float4 n0, n1;
        if (have_next) {
            n0 = W4[r_nxt * D4 + c0];
            n1 = W4[r_nxt * D4 + c1];
        }

        // consume current token
        float4 v0 = a0, v1 = a1;
        v0.x += bb0.x; v0.y += bb0.y; v0.z += bb0.z; v0.w += bb0.w;
        v1.x += bb1.x; v1.y += bb1.y; v1.z += bb1.z; v1.w += bb1.w;

        float4* __restrict__ dst = out4 + (long long)t * D4;
        __stcs(dst + c0, v0);
        __stcs(dst + c1, v1);

        if (!have_next) break;
        t = t1; t1 = t2;
        r_nxt = r_nxt2;
        a0 = n0; a1 = n1;
    }
}

extern "C" void kernel_launch(void* const* d_in, const int* in_sizes, int n_in,
                              void* d_out, int out_size) {
    const int*    x = (const int*)d_in[0];        // [4, 2048] int32
    const float4* W = (const float4*)d_in[1];     // [50257, 2048] f32
    const float4* b = (const float4*)d_in[2];     // [2048] f32
    float4* out = (float4*)d_out;                 // [4, 2048, 2048] f32

    embed_gather_pipe<<<GRID, NTHR>>>(x, W, b, out);
}